// round 17
// baseline (speedup 1.0000x reference)
#include <cuda_runtime.h>
#include <cuda_fp16.h>
#include <mma.h>
#include <cstdint>

using namespace nvcuda;

// ---------------------------------------------------------------------------
// out[b,t,f] = LayerNorm_f( spike( LIF(spikes@W + b) ) )
// alpha=exp(-50): recurrence degenerates (R1/R12-validated, rel_err 4e-8):
//   s[row,f] = ((spikes@W)[row,f] + b[f] > 0.5)
// WMMA fp16 2-split (Ah*Wh + Ah*Wl + Al*Wh, fp32 accum) + guarded exact fp32
// recompute + exact {0,1}-LayerNorm.
// R12 lesson: NO dynamic smem / cudaFuncSetAttribute. Static shared <= 41KB.
// R13 lesson: B-chunk staging covered only half the chunk (256 of 512 uint4,
// offset c*2 instead of c*4) -> rel_err 1.18. Fixed here: 2 iters, q in [0,4).
// Schedule: chunk-major K — A read+converted ONCE per CTA (was 3x in R12).
// ---------------------------------------------------------------------------

#define TSTEPS  256
#define IN_F    256
#define OUT_F   256
#define M_TOTAL 32768

__device__ __half   g_wt_hi[OUT_F * IN_F];   // W^T hi, [f][k]
__device__ __half   g_wt_lo[OUT_F * IN_F];   // W^T lo, [f][k]
__device__ uint32_t g_sbits[M_TOTAL * 8];    // spike bits, [row][8 words]

// ======================= Kernel 0: W^T + fp16 split ========================
__global__ void __launch_bounds__(256) prep_wt(const float* __restrict__ W) {
    __shared__ float tile[32][33];
    const int tx  = threadIdx.x & 31;
    const int ty0 = threadIdx.x >> 5;
    const int bi = blockIdx.y, bj = blockIdx.x;
    #pragma unroll
    for (int p = 0; p < 4; p++) {
        int ty = ty0 + p * 8;
        tile[ty][tx] = W[(bi * 32 + ty) * OUT_F + bj * 32 + tx];
    }
    __syncthreads();
    #pragma unroll
    for (int p = 0; p < 4; p++) {
        int ty = ty0 + p * 8;
        int f = bj * 32 + ty, i = bi * 32 + tx;
        float v = tile[tx][ty];
        __half h = __float2half_rn(v);
        __half l = __float2half_rn(v - __half2float(h));
        g_wt_hi[f * IN_F + i] = h;
        g_wt_lo[f * IN_F + i] = l;
    }
}

// ================= Kernel 1: GEMM + spike bits (static smem) ===============
// Grid 512 = 256 row-groups x 2 col-halves. 256 thr = 8 warps (2m x 4n).
// CTA tile 128 rows x 128 cols; warp tile 64x32 = 4x2 wmma tiles.
// K in 8 chunks of 32; per chunk: stage Ah,Al,Bh,Bl then 3 passes
// (Ah*Bh, Ah*Bl, Al*Bh) x 2 k-steps.
__global__ void __launch_bounds__(256) gemm_spike(
    const float* __restrict__ spikes,   // [M_TOTAL, IN_F]
    const float* __restrict__ W,        // fp32, for borderline recompute
    const float* __restrict__ bvec)     // [OUT_F]
{
    // 40KB raw shared; epilogue overlays the (dead) staging region.
    __shared__ __align__(16) char smbuf[40960];
    __half (*As)[128][40] = (__half(*)[128][40])(smbuf);            // [2][128][40]
    __half (*Bs)[128][40] = (__half(*)[128][40])(smbuf + 20480);    // [2][128][40]
    float*    Cw = (float*)smbuf;                 // epilogue: [8][256]
    uint32_t* sb = (uint32_t*)(smbuf + 8192);     // epilogue: [128][4]

    const int tid    = threadIdx.x;
    const int lane   = tid & 31;
    const int wid    = tid >> 5;
    const int warp_m = wid >> 2;        // 0..1
    const int warp_n = wid & 3;         // 0..3
    const int rowgrp = blockIdx.x >> 1;
    const int half   = blockIdx.x & 1;
    const int base_row = rowgrp * 128;
    const int base_col = half * 128;

    wmma::fragment<wmma::accumulator, 16, 16, 16, float> acc[4][2];
    #pragma unroll
    for (int mt = 0; mt < 4; mt++) {
        wmma::fill_fragment(acc[mt][0], 0.0f);
        wmma::fill_fragment(acc[mt][1], 0.0f);
    }

    const float4* Ag = (const float4*)spikes;          // row stride: 64 float4
    const uint4*  Bh = (const uint4*)g_wt_hi;          // row stride: 32 uint4
    const uint4*  Bl = (const uint4*)g_wt_lo;

    for (int c = 0; c < 8; c++) {                      // 8 chunks of k=32
        // ---- stage A chunk: 128 rows x 32 fp32 -> hi AND lo fp16
        #pragma unroll
        for (int it = 0; it < 4; it++) {
            int u = it * 256 + tid;                    // 1024 float4
            int row = u >> 3, kq = u & 7;              // kq: float4 within chunk
            float4 v = Ag[(size_t)(base_row + row) * 64 + c * 8 + kq];
            __half h0 = __float2half_rn(v.x), h1 = __float2half_rn(v.y);
            __half h2 = __float2half_rn(v.z), h3 = __float2half_rn(v.w);
            __half l0 = __float2half_rn(v.x - __half2float(h0));
            __half l1 = __float2half_rn(v.y - __half2float(h1));
            __half l2 = __float2half_rn(v.z - __half2float(h2));
            __half l3 = __float2half_rn(v.w - __half2float(h3));
            __half2 ph0 = __halves2half2(h0, h1), ph1 = __halves2half2(h2, h3);
            __half2 pl0 = __halves2half2(l0, l1), pl1 = __halves2half2(l2, l3);
            uint2 pkh, pkl;
            pkh.x = *(uint32_t*)&ph0; pkh.y = *(uint32_t*)&ph1;
            pkl.x = *(uint32_t*)&pl0; pkl.y = *(uint32_t*)&pl1;
            *(uint2*)&As[0][row][kq * 4] = pkh;
            *(uint2*)&As[1][row][kq * 4] = pkl;
        }
        // ---- stage B chunk: 128 f-rows x 32 halves = 512 uint4 per part
        #pragma unroll
        for (int it = 0; it < 2; it++) {
            int u = it * 256 + tid;                    // 512 uint4
            int n = u >> 2, q = u & 3;                 // 4 uint4 per row
            size_t gi = (size_t)(base_col + n) * 32 + c * 4 + q;
            *(uint4*)&Bs[0][n][q * 8] = Bh[gi];
            *(uint4*)&Bs[1][n][q * 8] = Bl[gi];
        }
        __syncthreads();

        // ---- 3 passes x 2 k-steps of WMMA on this chunk
        #pragma unroll
        for (int pass = 0; pass < 3; pass++) {
            const int pa = (pass == 2) ? 1 : 0;
            const int pb = (pass == 1) ? 1 : 0;
            #pragma unroll
            for (int ks = 0; ks < 2; ks++) {
                wmma::fragment<wmma::matrix_b, 16, 16, 16, __half,
                               wmma::col_major> b[2];
                wmma::load_matrix_sync(b[0], &Bs[pb][warp_n * 32][ks * 16], 40);
                wmma::load_matrix_sync(b[1], &Bs[pb][warp_n * 32 + 16][ks * 16], 40);
                #pragma unroll
                for (int mt = 0; mt < 4; mt++) {
                    wmma::fragment<wmma::matrix_a, 16, 16, 16, __half,
                                   wmma::row_major> a;
                    wmma::load_matrix_sync(a, &As[pa][warp_m * 64 + mt * 16][ks * 16], 40);
                    wmma::mma_sync(acc[mt][0], a, b[0], acc[mt][0]);
                    wmma::mma_sync(acc[mt][1], a, b[1], acc[mt][1]);
                }
            }
        }
        __syncthreads();
    }

    // ---- Epilogue (overlays staging smem): zero bit words first
    ((uint32_t*)sb)[tid]       = 0;
    ((uint32_t*)sb)[tid + 256] = 0;
    __syncthreads();

    const int r  = lane >> 1;           // 0..15 tile row
    const int c8 = (lane & 1) * 8;      // col-half within tile

    #pragma unroll
    for (int mt = 0; mt < 4; mt++) {
        #pragma unroll
        for (int nt = 0; nt < 2; nt++) {
            wmma::store_matrix_sync(&Cw[wid * 256], acc[mt][nt], 16,
                                    wmma::mem_row_major);
            __syncwarp();
            int lrow   = warp_m * 64 + mt * 16 + r;
            int colloc = warp_n * 32 + nt * 16 + c8;    // 0..127 within half
            int colg   = base_col + colloc;
            uint32_t bits = 0;
            #pragma unroll
            for (int i = 0; i < 8; i++) {
                float cur = Cw[wid * 256 + r * 16 + c8 + i] + bvec[colg + i];
                float cmp = cur - 0.5f;
                if (fabsf(cmp) < 1e-4f) {
                    // exact fp32 sequential-k recompute (matches ref ~1e-8)
                    int grow = base_row + lrow;
                    const float* sr = spikes + (size_t)grow * IN_F;
                    float a2 = 0.0f;
                    for (int kk = 0; kk < IN_F; kk++)
                        a2 = fmaf(sr[kk], W[(size_t)kk * OUT_F + colg + i], a2);
                    cmp = (a2 + bvec[colg + i]) - 0.5f;
                }
                if (cmp > 0.0f) bits |= 1u << i;
            }
            atomicOr(&sb[lrow * 4 + (colloc >> 5)], bits << (colloc & 31));
            __syncwarp();
        }
    }
    __syncthreads();

    // ---- flush bits: [row][8 words] global; this CTA owns words half*4..+3
    #pragma unroll
    for (int it = 0; it < 2; it++) {
        int u = it * 256 + tid;            // 512 words
        int row = u >> 2, w = u & 3;
        g_sbits[(size_t)(base_row + row) * 8 + half * 4 + w] = sb[row * 4 + w];
    }
}

// ================= Kernel 2: exact {0,1}-LayerNorm + store =================
__global__ void __launch_bounds__(256) ln_kernel(
    const float* __restrict__ gamma,    // [T, F]
    const float* __restrict__ beta,     // [T, F]
    float* __restrict__ out)            // [M_TOTAL, OUT_F]
{
    __shared__ uint32_t bits_s[128][8];
    __shared__ float2   stats[128];
    const int tid = threadIdx.x;
    const int base_row = blockIdx.x * 128;

    #pragma unroll
    for (int it = 0; it < 4; it++) {
        int u = it * 256 + tid;            // 1024 words
        ((uint32_t*)bits_s)[u] = g_sbits[(size_t)base_row * 8 + u];
    }
    __syncthreads();

    if (tid < 128) {
        int cnt = 0;
        #pragma unroll
        for (int w = 0; w < 8; w++) cnt += __popc(bits_s[tid][w]);
        float mu = (float)cnt * (1.0f / 256.0f);
        stats[tid] = make_float2(mu, rsqrtf(mu - mu * mu + 1e-6f));
    }
    __syncthreads();

    const int fo = tid;                     // one feature per thread
    const uint32_t wsel = fo >> 5, bsel = fo & 31;
    for (int row = 0; row < 128; row++) {
        float s = (float)((bits_s[row][wsel] >> bsel) & 1u);
        float2 st = stats[row];
        int grow = base_row + row;
        int t = grow & (TSTEPS - 1);
        out[(size_t)grow * OUT_F + fo] =
            (s - st.x) * st.y * gamma[(size_t)t * OUT_F + fo]
            + beta[(size_t)t * OUT_F + fo];
    }
}

// =============================== Launch ====================================
extern "C" void kernel_launch(void* const* d_in, const int* in_sizes, int n_in,
                              void* d_out, int out_size)
{
    const float* spikes   = (const float*)d_in[0];
    const float* W        = (const float*)d_in[1];
    const float* bvec     = (const float*)d_in[2];
    const float* ln_scale = (const float*)d_in[3];
    const float* ln_bias  = (const float*)d_in[4];
    float* out = (float*)d_out;

    prep_wt<<<dim3(8, 8), 256>>>(W);
    gemm_spike<<<512, 256>>>(spikes, W, bvec);
    ln_kernel<<<256, 256>>>(ln_scale, ln_bias, out);
}